// round 2
// baseline (speedup 1.0000x reference)
#include <cuda_runtime.h>
#include <cstdint>

// Problem constants (fixed shapes)
#define N_NODES   50000
#define N_EDGES   800000
#define S_DIM     128
#define BD_DIM    64
#define K_DIM     320
#define N_OUT     256      // sig(128) || soft(128)
#define TILE_E    128      // edges per CTA (M)
#define NSTAGE    10       // K stages of 32 floats
#define KC        32

// smem float-offsets
#define A_STRIDE  36       // padded A row (32 data + 4 pad)
#define B_STRIDE  264      // padded B row (256 data + 8 pad)
#define OFF_A0    0                         // 128*36 = 4608
#define OFF_A1    4608
#define OFF_B0    9216                      // 32*264 = 8448
#define OFF_B1    17664                     // buffers end at 26112
#define OFF_STAGE 0                         // epilogue staging 128*264 = 33792 (reuses buffers)
#define OFF_BSIG  33792
#define OFF_BSOFT 33920
#define OFF_SIDX  34048                     // 128 ints
#define SMEM_FLOATS 34176
#define SMEM_BYTES  (SMEM_FLOATS * 4)       // 136704

// ---------------- helpers ----------------
__device__ __forceinline__ void cp16(uint32_t dst_smem, const void* src) {
    asm volatile("cp.async.cg.shared.global [%0], [%1], 16;" :: "r"(dst_smem), "l"(src));
}
__device__ __forceinline__ void cp_commit() { asm volatile("cp.async.commit_group;"); }
__device__ __forceinline__ void cp_wait1()  { asm volatile("cp.async.wait_group 1;"); }
__device__ __forceinline__ void cp_wait0()  { asm volatile("cp.async.wait_group 0;"); }

__device__ __forceinline__ void mma_tf32(float* c, const uint32_t* a, const uint32_t* b) {
    asm volatile(
        "mma.sync.aligned.m16n8k8.row.col.f32.tf32.tf32.f32 "
        "{%0,%1,%2,%3}, {%4,%5,%6,%7}, {%8,%9}, {%0,%1,%2,%3};"
        : "+f"(c[0]), "+f"(c[1]), "+f"(c[2]), "+f"(c[3])
        : "r"(a[0]), "r"(a[1]), "r"(a[2]), "r"(a[3]), "r"(b[0]), "r"(b[1]));
}

__device__ __forceinline__ void red_add_v4(float* p, float a, float b, float c, float d) {
    asm volatile("red.global.add.v4.f32 [%0], {%1, %2, %3, %4};"
                 :: "l"(p), "f"(a), "f"(b), "f"(c), "f"(d) : "memory");
}

// residual init: out = sites
__global__ void copy_sites_kernel(const float4* __restrict__ src, float4* __restrict__ dst, int n4) {
    for (int i = blockIdx.x * blockDim.x + threadIdx.x; i < n4; i += gridDim.x * blockDim.x)
        dst[i] = src[i];
}

// ---------------- main fused kernel ----------------
__global__ void __launch_bounds__(512) edge_gate_kernel(
    const float* __restrict__ sites, const float* __restrict__ bonds,
    const float* __restrict__ W_sig, const float* __restrict__ b_sig,
    const float* __restrict__ W_soft, const float* __restrict__ b_soft,
    const int* __restrict__ idx1, const int* __restrict__ idx2,
    float* __restrict__ out)
{
    extern __shared__ float smf[];
    uint32_t sbase = (uint32_t)__cvta_generic_to_shared(smf);

    const int tid  = threadIdx.x;
    const int wid  = tid >> 5;
    const int lane = tid & 31;
    const int g    = lane >> 2;   // group id (rows)
    const int cc   = lane & 3;    // thread-in-group (k / col pairs)
    const int wm   = wid >> 2;    // warp M index 0..3 -> rows 32*wm
    const int wn   = wid & 3;     // warp N index 0..3 -> cols 64*wn
    const int tile0 = blockIdx.x * TILE_E;

    int* sidx = (int*)(smf + OFF_SIDX);
    float* bsig_s  = smf + OFF_BSIG;
    float* bsoft_s = smf + OFF_BSOFT;

    if (tid < 128) {
        sidx[tid]    = idx1[tile0 + tid];
        bsig_s[tid]  = b_sig[tid];
        bsoft_s[tid] = b_soft[tid];
    }

    // --- gather pointers for A loads: thread handles row r = tid>>2, 32B chunk (tid&3)*8 floats
    const int ar  = tid >> 2;
    const int ao  = (tid & 3) * 8;  // float offset within 32-float stage slice
    const int e   = tile0 + ar;
    const float* p1 = sites + (size_t)idx1[e] * S_DIM + ao;
    const float* p2 = sites + (size_t)idx2[e] * S_DIM + ao;
    const float* pb = bonds + (size_t)e * BD_DIM + ao;

    // A smem dst (bytes): row * 144 + (tid&3)*32
    const uint32_t a_dst_off = (uint32_t)(ar * (A_STRIDE * 4) + (tid & 3) * 32);

    // --- B loads: thread handles 4 chunks of 16B: q = tid*4 + j
    //   k = q>>6 (0..31 within stage), n16 = q&63 -> floats n = n16*4
    const int bq0 = tid * 4;

    // pipeline load of stage s into buffer (s&1)
    auto load_stage = [&](int s) {
        uint32_t abuf = sbase + ((s & 1) ? OFF_A1 * 4 : OFF_A0 * 4);
        uint32_t bbuf = sbase + ((s & 1) ? OFF_B1 * 4 : OFF_B0 * 4);
        const float* src = (s < 4) ? (p1 + s * KC)
                         : (s < 8) ? (p2 + (s - 4) * KC)
                                   : (pb + (s - 8) * KC);
        cp16(abuf + a_dst_off,      src);
        cp16(abuf + a_dst_off + 16, src + 4);
        const int kg0 = s * KC;
#pragma unroll
        for (int j = 0; j < 4; j++) {
            int q   = bq0 + j;
            int k   = q >> 6;
            int n16 = q & 63;
            int n   = n16 * 4;
            const float* bsrc = (n < 128) ? (W_sig  + (size_t)(kg0 + k) * 128 + n)
                                          : (W_soft + (size_t)(kg0 + k) * 128 + (n - 128));
            cp16(bbuf + (uint32_t)(k * (B_STRIDE * 4) + n16 * 16), bsrc);
        }
    };

    // prime
    load_stage(0); cp_commit();
    load_stage(1); cp_commit();

    float acc[2][8][4];
#pragma unroll
    for (int mt = 0; mt < 2; mt++)
#pragma unroll
        for (int nt = 0; nt < 8; nt++)
#pragma unroll
            for (int u = 0; u < 4; u++) acc[mt][nt][u] = 0.0f;

    for (int s = 0; s < NSTAGE; ++s) {
        if (s < NSTAGE - 1) cp_wait1(); else cp_wait0();
        __syncthreads();

        const float* As = smf + ((s & 1) ? OFF_A1 : OFF_A0);
        const float* Bs = smf + ((s & 1) ? OFF_B1 : OFF_B0);

#pragma unroll
        for (int k8 = 0; k8 < 4; k8++) {
            const int k0 = k8 * 8;
            uint32_t a[2][4];
#pragma unroll
            for (int mt = 0; mt < 2; mt++) {
                const uint32_t* ap = (const uint32_t*)(As + (32 * wm + 16 * mt + g) * A_STRIDE + k0 + cc);
                a[mt][0] = ap[0];
                a[mt][1] = ap[8 * A_STRIDE];
                a[mt][2] = ap[4];
                a[mt][3] = ap[8 * A_STRIDE + 4];
            }
            uint32_t b[8][2];
#pragma unroll
            for (int nt = 0; nt < 8; nt++) {
                const uint32_t* bp = (const uint32_t*)(Bs + (k0 + cc) * B_STRIDE + 64 * wn + 8 * nt + g);
                b[nt][0] = bp[0];
                b[nt][1] = bp[4 * B_STRIDE];
            }
#pragma unroll
            for (int mt = 0; mt < 2; mt++)
#pragma unroll
                for (int nt = 0; nt < 8; nt++)
                    mma_tf32(acc[mt][nt], a[mt], b[nt]);
        }

        __syncthreads();   // all warps done reading buffer (s&1)
        if (s + 2 < NSTAGE) { load_stage(s + 2); cp_commit(); }
    }

    // ---------------- epilogue ----------------
    // stage raw GEMM output [128][256] (stride 264) into smem (overwrites buffers; sync above done)
    float* stg = smf + OFF_STAGE;
#pragma unroll
    for (int mt = 0; mt < 2; mt++) {
#pragma unroll
        for (int nt = 0; nt < 8; nt++) {
            int r   = 32 * wm + 16 * mt + g;
            int col = 64 * wn + 8 * nt + 2 * cc;
            *(float2*)&stg[r * B_STRIDE + col]       = make_float2(acc[mt][nt][0], acc[mt][nt][1]);
            *(float2*)&stg[(r + 8) * B_STRIDE + col] = make_float2(acc[mt][nt][2], acc[mt][nt][3]);
        }
    }
    __syncthreads();

    // gate + scatter: thread handles row r = tid>>2, 32 gated cols starting (tid&3)*32
    {
        const int r  = tid >> 2;
        const int c0 = (tid & 3) * 32;
        float* dst = out + (size_t)sidx[r] * S_DIM + c0;
        const float* rs = &stg[r * B_STRIDE + c0];         // sig half
        const float* rf = &stg[r * B_STRIDE + 128 + c0];   // soft half
#pragma unroll
        for (int j = 0; j < 8; j++) {
            float4 xs = *(const float4*)(rs + 4 * j);
            float4 xf = *(const float4*)(rf + 4 * j);
            float v[4];
            const float* xsp = &xs.x;
            const float* xfp = &xf.x;
#pragma unroll
            for (int u = 0; u < 4; u++) {
                int col = c0 + 4 * j + u;
                float s_in = xsp[u] + bsig_s[col];
                float f_in = xfp[u] + bsoft_s[col];
                float sg = 1.0f / (1.0f + __expf(-s_in));
                v[u] = sg * fmaxf(f_in, 0.0f);
            }
            red_add_v4(dst + 4 * j, v[0], v[1], v[2], v[3]);
        }
    }
}

// ---------------- launch ----------------
extern "C" void kernel_launch(void* const* d_in, const int* in_sizes, int n_in,
                              void* d_out, int out_size) {
    const float* sites  = (const float*)d_in[0];
    const float* bonds  = (const float*)d_in[1];
    const float* W_sig  = (const float*)d_in[2];
    const float* b_sig  = (const float*)d_in[3];
    const float* W_soft = (const float*)d_in[4];
    const float* b_soft = (const float*)d_in[5];
    const int*   idx1   = (const int*)d_in[6];
    const int*   idx2   = (const int*)d_in[7];
    float* out = (float*)d_out;

    cudaFuncSetAttribute(edge_gate_kernel, cudaFuncAttributeMaxDynamicSharedMemorySize, SMEM_BYTES);

    int n4 = (N_NODES * S_DIM) / 4;
    copy_sites_kernel<<<1600, 256>>>((const float4*)sites, (float4*)d_out, n4);

    edge_gate_kernel<<<N_EDGES / TILE_E, 512, SMEM_BYTES>>>(
        sites, bonds, W_sig, b_sig, W_soft, b_soft, idx1, idx2, out);
}

// round 4
// speedup vs baseline: 1.6775x; 1.6775x over previous
#include <cuda_runtime.h>
#include <cstdint>

// Problem constants
#define N_NODES   50000
#define N_EDGES   800000
#define TILE_E    64
#define NTILES    12500       // 800000 / 64
#define GRID_EDGE 296         // 2 CTAs x 148 SMs

// ---- U table: [node][512] phys-interleaved; slot1(0:256)=U1(+bias), slot2(256:512)=U2
// phys col p in a 256 block: quad q=p>>3, half h=(p>>2)&1 (0=sig,1=soft), logical l=4q+(p&3)
static __device__ float g_U[(size_t)N_NODES * 512];

// ---------------- common helpers ----------------
__device__ __forceinline__ void cp16(uint32_t dst_smem, const void* src) {
    asm volatile("cp.async.cg.shared.global [%0], [%1], 16;" :: "r"(dst_smem), "l"(src));
}
__device__ __forceinline__ void cp_commit() { asm volatile("cp.async.commit_group;"); }
__device__ __forceinline__ void cp_wait1()  { asm volatile("cp.async.wait_group 1;"); }
__device__ __forceinline__ void cp_wait0()  { asm volatile("cp.async.wait_group 0;"); }

__device__ __forceinline__ void mma_tf32(float* c, const uint32_t* a, const uint32_t* b) {
    asm volatile(
        "mma.sync.aligned.m16n8k8.row.col.f32.tf32.tf32.f32 "
        "{%0,%1,%2,%3}, {%4,%5,%6,%7}, {%8,%9}, {%0,%1,%2,%3};"
        : "+f"(c[0]), "+f"(c[1]), "+f"(c[2]), "+f"(c[3])
        : "r"(a[0]), "r"(a[1]), "r"(a[2]), "r"(a[3]), "r"(b[0]), "r"(b[1]));
}

__device__ __forceinline__ void red_add_v2(float* p, float a, float b) {
    asm volatile("red.global.add.v2.f32 [%0], {%1, %2};" :: "l"(p), "f"(a), "f"(b) : "memory");
}

// residual init: out = sites
__global__ void copy_sites_kernel(const float4* __restrict__ src, float4* __restrict__ dst, int n4) {
    for (int i = blockIdx.x * blockDim.x + threadIdx.x; i < n4; i += gridDim.x * blockDim.x)
        dst[i] = src[i];
}

// ---------------- U precompute: U = sites @ Wcat[128,512] (phys-interleaved cols) ----------------
// tile M=128, N=128 (grid.y=4 covers 512), K=128 in 4 stages of 32, double-buffered
#define UG_ASTR 36
#define UG_BSTR 136
#define UG_A0   0
#define UG_A1   4608
#define UG_B0   9216
#define UG_B1   13568
#define UG_SMEMF 17920

__global__ void __launch_bounds__(256) u_gemm_kernel(
    const float* __restrict__ sites,
    const float* __restrict__ W_sig, const float* __restrict__ b_sig,
    const float* __restrict__ W_soft, const float* __restrict__ b_soft)
{
    extern __shared__ float smf[];
    uint32_t sbase = (uint32_t)__cvta_generic_to_shared(smf);

    const int tid = threadIdx.x, wid = tid >> 5, lane = tid & 31;
    const int g = lane >> 2, cc = lane & 3;
    const int wm = wid >> 1, wn = wid & 1;        // 4x2 warp grid, warp tile 32x64
    const int bm = blockIdx.x, by = blockIdx.y;
    const int row0 = bm * 128;

    auto load_stage = [&](int s) {
        uint32_t abuf = sbase + (uint32_t)(((s & 1) ? UG_A1 : UG_A0) * 4);
        uint32_t bbuf = sbase + (uint32_t)(((s & 1) ? UG_B1 : UG_B0) * 4);
#pragma unroll
        for (int j = 0; j < 4; j++) {           // A: 128 rows x 32 fl = 1024 chunks
            int q = tid + j * 256;
            int r = q >> 3, cx = q & 7;
            int grow = row0 + r; if (grow >= N_NODES) grow = N_NODES - 1;
            cp16(abuf + (uint32_t)((r * UG_ASTR + cx * 4) * 4),
                 sites + (size_t)grow * 128 + s * 32 + cx * 4);
        }
#pragma unroll
        for (int j = 0; j < 4; j++) {           // B: 32 k x 128 phys cols = 1024 chunks
            int q = tid + j * 256;
            int k = q >> 5, cq = q & 31;
            int P0 = by * 128 + cq * 4;
            int slot = P0 >> 8, p = P0 & 255;
            int h = (p >> 2) & 1, qd = p >> 3;
            const float* W = h ? W_soft : W_sig;
            cp16(bbuf + (uint32_t)((k * UG_BSTR + cq * 4) * 4),
                 W + (size_t)(slot * 128 + s * 32 + k) * 128 + qd * 4);
        }
    };

    load_stage(0); cp_commit();
    load_stage(1); cp_commit();

    float acc[2][8][4];
#pragma unroll
    for (int mt = 0; mt < 2; mt++)
#pragma unroll
        for (int nt = 0; nt < 8; nt++)
#pragma unroll
            for (int u = 0; u < 4; u++) acc[mt][nt][u] = 0.0f;

    for (int s = 0; s < 4; ++s) {
        if (s < 3) cp_wait1(); else cp_wait0();
        __syncthreads();
        const float* As = smf + ((s & 1) ? UG_A1 : UG_A0);
        const float* Bs = smf + ((s & 1) ? UG_B1 : UG_B0);
#pragma unroll
        for (int k8 = 0; k8 < 4; k8++) {
            const int k0 = k8 * 8;
            uint32_t a[2][4];
#pragma unroll
            for (int mt = 0; mt < 2; mt++) {
                const uint32_t* ap = (const uint32_t*)(As + (32 * wm + 16 * mt + g) * UG_ASTR + k0 + cc);
                a[mt][0] = ap[0]; a[mt][1] = ap[8 * UG_ASTR];
                a[mt][2] = ap[4]; a[mt][3] = ap[8 * UG_ASTR + 4];
            }
            uint32_t b[8][2];
#pragma unroll
            for (int nt = 0; nt < 8; nt++) {
                const uint32_t* bp = (const uint32_t*)(Bs + (k0 + cc) * UG_BSTR + 64 * wn + 8 * nt + g);
                b[nt][0] = bp[0]; b[nt][1] = bp[4 * UG_BSTR];
            }
#pragma unroll
            for (int mt = 0; mt < 2; mt++)
#pragma unroll
                for (int nt = 0; nt < 8; nt++)
                    mma_tf32(acc[mt][nt], a[mt], b[nt]);
        }
        __syncthreads();
        if (s + 2 < 4) { load_stage(s + 2); cp_commit(); }
    }

    // epilogue: write U (+bias on slot1)
#pragma unroll
    for (int mt = 0; mt < 2; mt++) {
        int r_lo = 32 * wm + 16 * mt + g;
        int grow_lo = row0 + r_lo, grow_hi = grow_lo + 8;
#pragma unroll
        for (int nt = 0; nt < 8; nt++) {
            int col = 64 * wn + 8 * nt + 2 * cc;
            int P = by * 128 + col;
            float bb0 = 0.0f, bb1 = 0.0f;
            if (by < 2) {                        // slot1: fold bias
                int p = P & 255;
                int h = (p >> 2) & 1;
                int l = ((p >> 3) << 2) | (p & 3);
                const float* bv = h ? b_soft : b_sig;
                bb0 = bv[l]; bb1 = bv[l + 1];
            }
            if (grow_lo < N_NODES)
                *(float2*)(g_U + (size_t)grow_lo * 512 + P) =
                    make_float2(acc[mt][nt][0] + bb0, acc[mt][nt][1] + bb1);
            if (grow_hi < N_NODES)
                *(float2*)(g_U + (size_t)grow_hi * 512 + P) =
                    make_float2(acc[mt][nt][2] + bb0, acc[mt][nt][3] + bb1);
        }
    }
}

// ---------------- edge kernel: bonds @ Wb + gather(U) + gate + scatter ----------------
// persistent CTAs, 256 thr, tile 64 edges, N=256 phys-interleaved, K=64 (no K loop)
#define EG_ASTR  68
#define EG_BSTR  264
#define EG_OFF_B    0            // 64 x 264 = 16896 fl (loaded once)
#define EG_OFF_A0   16896        // 64 x 68 = 4352 fl
#define EG_OFF_A1   21248
#define EG_OFF_IDX0 25600        // 128 ints (i1[64] | i2[64])
#define EG_OFF_IDX1 25728
#define EG_SMEMF    25856
#define EG_SMEMB    (EG_SMEMF * 4)   // 103424

__global__ void __launch_bounds__(256, 2) edge_gate_kernel(
    const float* __restrict__ bonds,
    const float* __restrict__ W_sig, const float* __restrict__ W_soft,
    const int* __restrict__ idx1, const int* __restrict__ idx2,
    float* __restrict__ out)
{
    extern __shared__ float smf[];
    uint32_t sbase = (uint32_t)__cvta_generic_to_shared(smf);

    const int tid = threadIdx.x, wid = tid >> 5, lane = tid & 31;
    const int g = lane >> 2, cc = lane & 3;
    const int wm = wid >> 2, wn = wid & 3;       // 2x4 warp grid, warp tile 32x64

    // load B (Wb rows 256:320, phys-interleaved cols) once:
    // 64 k-rows x 256 phys cols = 4096 chunks of 16B  (FIXED: was 2048 covering half)
#pragma unroll
    for (int j = 0; j < 16; j++) {
        int q = tid + j * 256;                   // 0..4095
        int k = q >> 6, cq = q & 63;             // phys cols 4cq..4cq+3
        int h = cq & 1, qd = cq >> 1;
        const float* W = h ? W_soft : W_sig;
        cp16(sbase + (uint32_t)((k * EG_BSTR + cq * 4) * 4),
             W + (size_t)(256 + k) * 128 + qd * 4);
    }

    auto load_A = [&](int t, int buf) {
        uint32_t abuf = sbase + (uint32_t)((EG_OFF_A0 + buf * 4352) * 4);
        uint32_t ibuf = sbase + (uint32_t)((EG_OFF_IDX0 + buf * 128) * 4);
#pragma unroll
        for (int j = 0; j < 4; j++) {            // bonds: 64 rows x 64 fl = 1024 chunks
            int q = tid + j * 256;
            int r = q >> 4, cx = q & 15;
            cp16(abuf + (uint32_t)((r * EG_ASTR + cx * 4) * 4),
                 bonds + (size_t)(t * TILE_E + r) * 64 + cx * 4);
        }
        if (tid < 32) {                          // indices: 32 chunks
            const int* src = (tid < 16) ? (idx1 + t * TILE_E + (tid & 15) * 4)
                                        : (idx2 + t * TILE_E + (tid & 15) * 4);
            cp16(ibuf + (uint32_t)((((tid < 16) ? 0 : 64) + (tid & 15) * 4) * 4), src);
        }
    };

    int tile = blockIdx.x;
    load_A(tile, 0); cp_commit();                // group: B + A0 + idx0

    int it = 0;
    while (true) {
        int next = tile + GRID_EDGE;
        bool have_next = (next < NTILES);
        if (have_next) { load_A(next, (it + 1) & 1); cp_commit(); }
        if (have_next) cp_wait1(); else cp_wait0();
        __syncthreads();

        const float* As = smf + EG_OFF_A0 + (it & 1) * 4352;
        const float* Bs = smf + EG_OFF_B;

        float acc[2][8][4];
#pragma unroll
        for (int mt = 0; mt < 2; mt++)
#pragma unroll
            for (int nt = 0; nt < 8; nt++)
#pragma unroll
                for (int u = 0; u < 4; u++) acc[mt][nt][u] = 0.0f;

#pragma unroll
        for (int k8 = 0; k8 < 8; k8++) {
            const int k0 = k8 * 8;
            uint32_t a[2][4];
#pragma unroll
            for (int mt = 0; mt < 2; mt++) {
                const uint32_t* ap = (const uint32_t*)(As + (32 * wm + 16 * mt + g) * EG_ASTR + k0 + cc);
                a[mt][0] = ap[0]; a[mt][1] = ap[8 * EG_ASTR];
                a[mt][2] = ap[4]; a[mt][3] = ap[8 * EG_ASTR + 4];
            }
            uint32_t b[8][2];
#pragma unroll
            for (int nt = 0; nt < 8; nt++) {
                const uint32_t* bp = (const uint32_t*)(Bs + (k0 + cc) * EG_BSTR + 64 * wn + 8 * nt + g);
                b[nt][0] = bp[0]; b[nt][1] = bp[4 * EG_BSTR];
            }
#pragma unroll
            for (int mt = 0; mt < 2; mt++)
#pragma unroll
                for (int nt = 0; nt < 8; nt++)
                    mma_tf32(acc[mt][nt], a[mt], b[nt]);
        }

        // ---- epilogue: + U1[i1] + U2[i2], in-register gate via shfl, v2 scatter ----
        const int* sidx = (const int*)(smf + EG_OFF_IDX0 + (it & 1) * 128);
        const int cb = 64 * wn + 2 * cc;
#pragma unroll
        for (int mt = 0; mt < 2; mt++) {
            int r_lo = 32 * wm + 16 * mt + g;
            int r_hi = r_lo + 8;
            int i1lo = sidx[r_lo], i2lo = sidx[64 + r_lo];
            int i1hi = sidx[r_hi], i2hi = sidx[64 + r_hi];
            const float* U1lo = g_U + (size_t)i1lo * 512;
            const float* U2lo = g_U + (size_t)i2lo * 512 + 256;
            const float* U1hi = g_U + (size_t)i1hi * 512;
            const float* U2hi = g_U + (size_t)i2hi * 512 + 256;
            float* outlo = out + (size_t)i1lo * 128;
            float* outhi = out + (size_t)i1hi * 128;
#pragma unroll
            for (int nt = 0; nt < 8; nt++) {
                int c = cb + 8 * nt;
                float2 ua = *(const float2*)(U1lo + c);
                float2 ub = *(const float2*)(U2lo + c);
                float2 va = *(const float2*)(U1hi + c);
                float2 vb = *(const float2*)(U2hi + c);
                float x0 = acc[mt][nt][0] + ua.x + ub.x;
                float x1 = acc[mt][nt][1] + ua.y + ub.y;
                float y0 = acc[mt][nt][2] + va.x + vb.x;
                float y1 = acc[mt][nt][3] + va.y + vb.y;
                // exchange sig<->soft halves (cc^2 partner)
                float rx0 = __shfl_xor_sync(0xFFFFFFFFu, x0, 2);
                float rx1 = __shfl_xor_sync(0xFFFFFFFFu, x1, 2);
                float ry0 = __shfl_xor_sync(0xFFFFFFFFu, y0, 2);
                float ry1 = __shfl_xor_sync(0xFFFFFFFFu, y1, 2);
                float sg0, sg1, sf0, sf1;
                float* dst;
                if ((cc & 2) == 0) {   // compute row_lo: own = sig, recv = soft
                    sg0 = x0; sg1 = x1; sf0 = rx0; sf1 = rx1; dst = outlo;
                } else {               // compute row_hi: recv = sig, own = soft
                    sg0 = ry0; sg1 = ry1; sf0 = y0; sf1 = y1; dst = outhi;
                }
                float v0 = (1.0f / (1.0f + __expf(-sg0))) * fmaxf(sf0, 0.0f);
                float v1 = (1.0f / (1.0f + __expf(-sg1))) * fmaxf(sf1, 0.0f);
                int gcol = 32 * wn + 4 * nt + 2 * (cc & 1);
                red_add_v2(dst + gcol, v0, v1);
            }
        }

        __syncthreads();
        if (!have_next) break;
        tile = next; it++;
    }
}

// ---------------- launch ----------------
extern "C" void kernel_launch(void* const* d_in, const int* in_sizes, int n_in,
                              void* d_out, int out_size) {
    const float* sites  = (const float*)d_in[0];
    const float* bonds  = (const float*)d_in[1];
    const float* W_sig  = (const float*)d_in[2];
    const float* b_sig  = (const float*)d_in[3];
    const float* W_soft = (const float*)d_in[4];
    const float* b_soft = (const float*)d_in[5];
    const int*   idx1   = (const int*)d_in[6];
    const int*   idx2   = (const int*)d_in[7];
    float* out = (float*)d_out;

    cudaFuncSetAttribute(u_gemm_kernel, cudaFuncAttributeMaxDynamicSharedMemorySize, UG_SMEMF * 4);
    cudaFuncSetAttribute(edge_gate_kernel, cudaFuncAttributeMaxDynamicSharedMemorySize, EG_SMEMB);

    // 1) residual init: out = sites
    int n4 = (N_NODES * 128) / 4;
    copy_sites_kernel<<<1600, 256>>>((const float4*)sites, (float4*)out, n4);

    // 2) U = sites @ Wcat (bias folded into slot1)
    u_gemm_kernel<<<dim3((N_NODES + 127) / 128, 4), 256, UG_SMEMF * 4>>>(
        sites, W_sig, b_sig, W_soft, b_soft);

    // 3) edges: bonds @ Wb + U gather + gate + scatter
    edge_gate_kernel<<<GRID_EDGE, 256, EG_SMEMB>>>(
        bonds, W_sig, W_soft, idx1, idx2, out);
}

// round 5
// speedup vs baseline: 2.2540x; 1.3436x over previous
#include <cuda_runtime.h>
#include <cstdint>

// Problem constants
#define N_NODES   50000
#define N_EDGES   800000
#define TILE_E    64
#define NTILES    12500       // 800000 / 64
#define GRID_EDGE 296         // 2 CTAs x 148 SMs
#define NB50      50176       // 196 * 256 (padded node count for scan)

// ---- U table: [node][512] phys-interleaved; slot1(0:256)=U1(+bias), slot2(256:512)=U2
// phys col p in a 256 block: quad q=p>>3, half h=(p>>2)&1 (0=sig,1=soft), logical l=4q+(p&3)
static __device__ float g_U[(size_t)N_NODES * 512];
static __device__ int   g_count[NB50];     // hist -> local-exclusive scan -> perm cursors
static __device__ int   g_bsum[256];       // block sums -> exclusive block offsets
static __device__ int   g_perm[N_EDGES];   // edge ids sorted by idx1

// ---------------- common helpers ----------------
__device__ __forceinline__ void cp16(uint32_t dst_smem, const void* src) {
    asm volatile("cp.async.cg.shared.global [%0], [%1], 16;" :: "r"(dst_smem), "l"(src));
}
__device__ __forceinline__ void cp_commit() { asm volatile("cp.async.commit_group;"); }
__device__ __forceinline__ void cp_wait0()  { asm volatile("cp.async.wait_group 0;"); }

__device__ __forceinline__ void mma_tf32(float* c, const uint32_t* a, const uint32_t* b) {
    asm volatile(
        "mma.sync.aligned.m16n8k8.row.col.f32.tf32.tf32.f32 "
        "{%0,%1,%2,%3}, {%4,%5,%6,%7}, {%8,%9}, {%0,%1,%2,%3};"
        : "+f"(c[0]), "+f"(c[1]), "+f"(c[2]), "+f"(c[3])
        : "r"(a[0]), "r"(a[1]), "r"(a[2]), "r"(a[3]), "r"(b[0]), "r"(b[1]));
}

__device__ __forceinline__ void red_add_v2(float* p, float a, float b) {
    asm volatile("red.global.add.v2.f32 [%0], {%1, %2};" :: "l"(p), "f"(a), "f"(b) : "memory");
}

// ---------------- sort kernels ----------------
__global__ void hist_kernel(const int* __restrict__ idx1) {
    int e = blockIdx.x * blockDim.x + threadIdx.x;
    if (e < N_EDGES) atomicAdd(&g_count[idx1[e]], 1);
}

// per-block scan: g_count[i] -> local exclusive prefix; g_bsum[b] = block total
__global__ void scan_a_kernel() {
    __shared__ int s[256];
    int t = threadIdx.x, b = blockIdx.x;
    int i = b * 256 + t;
    int c = g_count[i];
    s[t] = c; __syncthreads();
#pragma unroll
    for (int d = 1; d < 256; d <<= 1) {
        int v = (t >= d) ? s[t - d] : 0; __syncthreads();
        s[t] += v; __syncthreads();
    }
    g_count[i] = s[t] - c;
    if (t == 255) g_bsum[b] = s[255];
}

// single-block exclusive scan of 196 block sums
__global__ void scan_b_kernel() {
    __shared__ int s[256];
    int t = threadIdx.x;
    int c = (t < 196) ? g_bsum[t] : 0;
    s[t] = c; __syncthreads();
#pragma unroll
    for (int d = 1; d < 256; d <<= 1) {
        int v = (t >= d) ? s[t - d] : 0; __syncthreads();
        s[t] += v; __syncthreads();
    }
    g_bsum[t] = s[t] - c;
}

// perm scatter: pos = blockoff + localexcl + in-bucket cursor
__global__ void perm_kernel(const int* __restrict__ idx1) {
    int e = blockIdx.x * blockDim.x + threadIdx.x;
    if (e < N_EDGES) {
        int n = idx1[e];
        int local = atomicAdd(&g_count[n], 1);
        g_perm[local + g_bsum[n >> 8]] = e;
    }
}

// ---------------- U precompute (fused: zero g_count + residual copy + GEMM) ----------------
// tile M=128, N=128 (grid.y=4 covers 512), K=128 in 4 stages of 32, double-buffered
#define UG_ASTR 36
#define UG_BSTR 136
#define UG_A0   0
#define UG_A1   4608
#define UG_B0   9216
#define UG_B1   13568
#define UG_SMEMF 17920

__global__ void __launch_bounds__(256) u_gemm_kernel(
    const float* __restrict__ sites,
    const float* __restrict__ W_sig, const float* __restrict__ b_sig,
    const float* __restrict__ W_soft, const float* __restrict__ b_soft,
    float* __restrict__ out)
{
    extern __shared__ float smf[];
    uint32_t sbase = (uint32_t)__cvta_generic_to_shared(smf);

    const int tid = threadIdx.x, wid = tid >> 5, lane = tid & 31;
    const int g = lane >> 2, cc = lane & 3;
    const int wm = wid >> 1, wn = wid & 1;        // 4x2 warp grid, warp tile 32x64
    const int bm = blockIdx.x, by = blockIdx.y;
    const int row0 = bm * 128;

    // ---- fused housekeeping: zero g_count, residual copy out = sites ----
    {
        int gid = (by * gridDim.x + bm) * 256 + tid;
        int nthr = gridDim.x * gridDim.y * 256;
        if (gid < NB50) g_count[gid] = 0;
        const float4* s4 = (const float4*)sites;
        float4* o4 = (float4*)out;
        for (int i = gid; i < (N_NODES * 128) / 4; i += nthr) o4[i] = s4[i];
    }

    auto load_stage = [&](int s) {
        uint32_t abuf = sbase + (uint32_t)(((s & 1) ? UG_A1 : UG_A0) * 4);
        uint32_t bbuf = sbase + (uint32_t)(((s & 1) ? UG_B1 : UG_B0) * 4);
#pragma unroll
        for (int j = 0; j < 4; j++) {           // A: 128 rows x 32 fl = 1024 chunks
            int q = tid + j * 256;
            int r = q >> 3, cx = q & 7;
            int grow = row0 + r; if (grow >= N_NODES) grow = N_NODES - 1;
            cp16(abuf + (uint32_t)((r * UG_ASTR + cx * 4) * 4),
                 sites + (size_t)grow * 128 + s * 32 + cx * 4);
        }
#pragma unroll
        for (int j = 0; j < 4; j++) {           // B: 32 k x 128 phys cols = 1024 chunks
            int q = tid + j * 256;
            int k = q >> 5, cq = q & 31;
            int P0 = by * 128 + cq * 4;
            int slot = P0 >> 8, p = P0 & 255;
            int h = (p >> 2) & 1, qd = p >> 3;
            const float* W = h ? W_soft : W_sig;
            cp16(bbuf + (uint32_t)((k * UG_BSTR + cq * 4) * 4),
                 W + (size_t)(slot * 128 + s * 32 + k) * 128 + qd * 4);
        }
    };

    load_stage(0); cp_commit();
    load_stage(1); cp_commit();

    float acc[2][8][4];
#pragma unroll
    for (int mt = 0; mt < 2; mt++)
#pragma unroll
        for (int nt = 0; nt < 8; nt++)
#pragma unroll
            for (int u = 0; u < 4; u++) acc[mt][nt][u] = 0.0f;

    for (int s = 0; s < 4; ++s) {
        if (s < 3) { asm volatile("cp.async.wait_group 1;"); } else cp_wait0();
        __syncthreads();
        const float* As = smf + ((s & 1) ? UG_A1 : UG_A0);
        const float* Bs = smf + ((s & 1) ? UG_B1 : UG_B0);
#pragma unroll
        for (int k8 = 0; k8 < 4; k8++) {
            const int k0 = k8 * 8;
            uint32_t a[2][4];
#pragma unroll
            for (int mt = 0; mt < 2; mt++) {
                const uint32_t* ap = (const uint32_t*)(As + (32 * wm + 16 * mt + g) * UG_ASTR + k0 + cc);
                a[mt][0] = ap[0]; a[mt][1] = ap[8 * UG_ASTR];
                a[mt][2] = ap[4]; a[mt][3] = ap[8 * UG_ASTR + 4];
            }
            uint32_t b[8][2];
#pragma unroll
            for (int nt = 0; nt < 8; nt++) {
                const uint32_t* bp = (const uint32_t*)(Bs + (k0 + cc) * UG_BSTR + 64 * wn + 8 * nt + g);
                b[nt][0] = bp[0]; b[nt][1] = bp[4 * UG_BSTR];
            }
#pragma unroll
            for (int mt = 0; mt < 2; mt++)
#pragma unroll
                for (int nt = 0; nt < 8; nt++)
                    mma_tf32(acc[mt][nt], a[mt], b[nt]);
        }
        __syncthreads();
        if (s + 2 < 4) { load_stage(s + 2); cp_commit(); }
    }

    // epilogue: write U (+bias on slot1)
#pragma unroll
    for (int mt = 0; mt < 2; mt++) {
        int r_lo = 32 * wm + 16 * mt + g;
        int grow_lo = row0 + r_lo, grow_hi = grow_lo + 8;
#pragma unroll
        for (int nt = 0; nt < 8; nt++) {
            int col = 64 * wn + 8 * nt + 2 * cc;
            int P = by * 128 + col;
            float bb0 = 0.0f, bb1 = 0.0f;
            if (by < 2) {                        // slot1: fold bias
                int p = P & 255;
                int h = (p >> 2) & 1;
                int l = ((p >> 3) << 2) | (p & 3);
                const float* bv = h ? b_soft : b_sig;
                bb0 = bv[l]; bb1 = bv[l + 1];
            }
            if (grow_lo < N_NODES)
                *(float2*)(g_U + (size_t)grow_lo * 512 + P) =
                    make_float2(acc[mt][nt][0] + bb0, acc[mt][nt][1] + bb1);
            if (grow_hi < N_NODES)
                *(float2*)(g_U + (size_t)grow_hi * 512 + P) =
                    make_float2(acc[mt][nt][2] + bb0, acc[mt][nt][3] + bb1);
        }
    }
}

// ---------------- edge kernel (sorted): bonds[perm] @ Wb + gather(U) + gate + scatter ----------------
#define EG_ASTR  68
#define EG_BSTR  264
#define EG_OFF_B    0            // 64 x 264 = 16896 fl (loaded once)
#define EG_OFF_A0   16896        // 64 x 68 = 4352 fl per buffer
#define EG_OFF_IDX  25600        // 2 buffers x 192 ints: [perm 64 | i1 64 | i2 64]
#define EG_SMEMF    25984
#define EG_SMEMB    (EG_SMEMF * 4)   // 103936

__global__ void __launch_bounds__(256, 2) edge_gate_kernel(
    const float* __restrict__ bonds,
    const float* __restrict__ W_sig, const float* __restrict__ W_soft,
    const int* __restrict__ idx1, const int* __restrict__ idx2,
    float* __restrict__ out)
{
    extern __shared__ float smf[];
    uint32_t sbase = (uint32_t)__cvta_generic_to_shared(smf);

    const int tid = threadIdx.x, wid = tid >> 5, lane = tid & 31;
    const int g = lane >> 2, cc = lane & 3;
    const int wm = wid >> 2, wn = wid & 3;       // 2x4 warp grid, warp tile 32x64

    // load B (Wb rows 256:320, phys-interleaved cols) once: 64 k x 256 phys = 4096 chunks
#pragma unroll
    for (int j = 0; j < 16; j++) {
        int q = tid + j * 256;
        int k = q >> 6, cq = q & 63;
        int h = cq & 1, qd = cq >> 1;
        const float* W = h ? W_soft : W_sig;
        cp16(sbase + (uint32_t)((k * EG_BSTR + cq * 4) * 4),
             W + (size_t)(256 + k) * 128 + qd * 4);
    }

    int* islot = (int*)(smf + EG_OFF_IDX);   // [buf*192 + {perm:0, i1:64, i2:128}]

    auto load_A_cp = [&](int buf) {          // gather bond rows via smem perm of this buffer
        const int* sp = islot + buf * 192;
        uint32_t abuf = sbase + (uint32_t)((EG_OFF_A0 + buf * 4352) * 4);
#pragma unroll
        for (int j = 0; j < 4; j++) {        // 64 rows x 64 fl = 1024 chunks
            int q = tid + j * 256;
            int r = q >> 4, cx = q & 15;
            cp16(abuf + (uint32_t)((r * EG_ASTR + cx * 4) * 4),
                 bonds + (size_t)sp[r] * 64 + cx * 4);
        }
    };

    // ---- prologue ----
    int tile = blockIdx.x;
    if (tid < 64) {
        int p = g_perm[tile * TILE_E + tid];
        islot[tid] = p; islot[64 + tid] = idx1[p]; islot[128 + tid] = idx2[p];
    }
    __syncthreads();
    load_A_cp(0); cp_commit();               // group 0: B + A(tile0)

    int p_r = 0, a_r = 0, b_r = 0;
    {
        int nx = tile + GRID_EDGE;
        if (tid < 64 && nx < NTILES) {
            p_r = g_perm[nx * TILE_E + tid]; a_r = idx1[p_r]; b_r = idx2[p_r];
        }
    }

    int it = 0;
    while (true) {
        int buf = it & 1;
        int next = tile + GRID_EDGE;
        bool have_next = (next < NTILES);

        cp_wait0(); __syncthreads();         // A(tile) ready; prior epilogue done

        if (have_next && tid < 64) {
            int* d = islot + (buf ^ 1) * 192;
            d[tid] = p_r; d[64 + tid] = a_r; d[128 + tid] = b_r;
        }
        __syncthreads();                     // perm(next) visible
        if (have_next) { load_A_cp(buf ^ 1); cp_commit(); }

        int nn = next + GRID_EDGE;
        if (have_next && tid < 64 && nn < NTILES) {   // hidden under GEMM
            p_r = g_perm[nn * TILE_E + tid]; a_r = idx1[p_r]; b_r = idx2[p_r];
        }

        const float* As = smf + EG_OFF_A0 + buf * 4352;
        const float* Bs = smf + EG_OFF_B;

        float acc[2][8][4];
#pragma unroll
        for (int mt = 0; mt < 2; mt++)
#pragma unroll
            for (int nt = 0; nt < 8; nt++)
#pragma unroll
                for (int u = 0; u < 4; u++) acc[mt][nt][u] = 0.0f;

#pragma unroll
        for (int k8 = 0; k8 < 8; k8++) {
            const int k0 = k8 * 8;
            uint32_t a[2][4];
#pragma unroll
            for (int mt = 0; mt < 2; mt++) {
                const uint32_t* ap = (const uint32_t*)(As + (32 * wm + 16 * mt + g) * EG_ASTR + k0 + cc);
                a[mt][0] = ap[0]; a[mt][1] = ap[8 * EG_ASTR];
                a[mt][2] = ap[4]; a[mt][3] = ap[8 * EG_ASTR + 4];
            }
            uint32_t b[8][2];
#pragma unroll
            for (int nt = 0; nt < 8; nt++) {
                const uint32_t* bp = (const uint32_t*)(Bs + (k0 + cc) * EG_BSTR + 64 * wn + 8 * nt + g);
                b[nt][0] = bp[0]; b[nt][1] = bp[4 * EG_BSTR];
            }
#pragma unroll
            for (int mt = 0; mt < 2; mt++)
#pragma unroll
                for (int nt = 0; nt < 8; nt++)
                    mma_tf32(acc[mt][nt], a[mt], b[nt]);
        }

        // ---- epilogue: + U1[i1] + U2[i2], in-register gate via shfl, v2 scatter ----
        const int* sidx = islot + buf * 192;
        const int cb = 64 * wn + 2 * cc;
#pragma unroll
        for (int mt = 0; mt < 2; mt++) {
            int r_lo = 32 * wm + 16 * mt + g;
            int r_hi = r_lo + 8;
            int i1lo = sidx[64 + r_lo], i2lo = sidx[128 + r_lo];
            int i1hi = sidx[64 + r_hi], i2hi = sidx[128 + r_hi];
            const float* U1lo = g_U + (size_t)i1lo * 512;
            const float* U2lo = g_U + (size_t)i2lo * 512 + 256;
            const float* U1hi = g_U + (size_t)i1hi * 512;
            const float* U2hi = g_U + (size_t)i2hi * 512 + 256;
            float* outlo = out + (size_t)i1lo * 128;
            float* outhi = out + (size_t)i1hi * 128;
#pragma unroll
            for (int nt = 0; nt < 8; nt++) {
                int c = cb + 8 * nt;
                float2 ua = __ldg((const float2*)(U1lo + c));
                float2 ub = __ldg((const float2*)(U2lo + c));
                float2 va = __ldg((const float2*)(U1hi + c));
                float2 vb = __ldg((const float2*)(U2hi + c));
                float x0 = acc[mt][nt][0] + ua.x + ub.x;
                float x1 = acc[mt][nt][1] + ua.y + ub.y;
                float y0 = acc[mt][nt][2] + va.x + vb.x;
                float y1 = acc[mt][nt][3] + va.y + vb.y;
                // exchange sig<->soft halves (cc^2 partner)
                float rx0 = __shfl_xor_sync(0xFFFFFFFFu, x0, 2);
                float rx1 = __shfl_xor_sync(0xFFFFFFFFu, x1, 2);
                float ry0 = __shfl_xor_sync(0xFFFFFFFFu, y0, 2);
                float ry1 = __shfl_xor_sync(0xFFFFFFFFu, y1, 2);
                float sg0, sg1, sf0, sf1;
                float* dst;
                if ((cc & 2) == 0) {   // compute row_lo: own = sig, recv = soft
                    sg0 = x0; sg1 = x1; sf0 = rx0; sf1 = rx1; dst = outlo;
                } else {               // compute row_hi: recv = sig, own = soft
                    sg0 = ry0; sg1 = ry1; sf0 = y0; sf1 = y1; dst = outhi;
                }
                float v0 = (1.0f / (1.0f + __expf(-sg0))) * fmaxf(sf0, 0.0f);
                float v1 = (1.0f / (1.0f + __expf(-sg1))) * fmaxf(sf1, 0.0f);
                int gcol = 32 * wn + 4 * nt + 2 * (cc & 1);
                red_add_v2(dst + gcol, v0, v1);
            }
        }

        if (!have_next) break;
        tile = next; ++it;
    }
}

// ---------------- launch ----------------
extern "C" void kernel_launch(void* const* d_in, const int* in_sizes, int n_in,
                              void* d_out, int out_size) {
    const float* sites  = (const float*)d_in[0];
    const float* bonds  = (const float*)d_in[1];
    const float* W_sig  = (const float*)d_in[2];
    const float* b_sig  = (const float*)d_in[3];
    const float* W_soft = (const float*)d_in[4];
    const float* b_soft = (const float*)d_in[5];
    const int*   idx1   = (const int*)d_in[6];
    const int*   idx2   = (const int*)d_in[7];
    float* out = (float*)d_out;

    cudaFuncSetAttribute(u_gemm_kernel, cudaFuncAttributeMaxDynamicSharedMemorySize, UG_SMEMF * 4);
    cudaFuncSetAttribute(edge_gate_kernel, cudaFuncAttributeMaxDynamicSharedMemorySize, EG_SMEMB);

    // 1) U = sites @ Wcat (fused: zero g_count + out=sites residual copy)
    u_gemm_kernel<<<dim3((N_NODES + 127) / 128, 4), 256, UG_SMEMF * 4>>>(
        sites, W_sig, b_sig, W_soft, b_soft, out);

    // 2-5) counting sort of edges by idx1
    hist_kernel<<<N_EDGES / 256, 256>>>(idx1);
    scan_a_kernel<<<NB50 / 256, 256>>>();
    scan_b_kernel<<<1, 256>>>();
    perm_kernel<<<N_EDGES / 256, 256>>>(idx1);

    // 6) edges (sorted): bonds[perm] @ Wb + U gather + gate + scatter
    edge_gate_kernel<<<GRID_EDGE, 256, EG_SMEMB>>>(
        bonds, W_sig, W_soft, idx1, idx2, out);
}

// round 8
// speedup vs baseline: 2.3214x; 1.0299x over previous
#include <cuda_runtime.h>
#include <cstdint>

// Problem constants
#define N_NODES   50000
#define N_EDGES   800000
#define TILE_E    64
#define NTILES    12500       // 800000 / 64
#define GRID_EDGE 296         // 2 CTAs x 148 SMs
#define NB50      50176       // 196 * 256 (padded node count for scan)

// ---- U table: [node][512] phys-interleaved; slot1(0:256)=U1(+bias), slot2(256:512)=U2
// phys col p in a 256 block: quad q=p>>3, half h=(p>>2)&1 (0=sig,1=soft), logical l=4q+(p&3)
static __device__ float g_U[(size_t)N_NODES * 512];
static __device__ int   g_count[NB50];     // hist -> local-exclusive scan -> perm cursors
static __device__ int   g_bsum[256];       // block sums -> exclusive block offsets
static __device__ int   g_perm[N_EDGES];   // edge ids sorted by idx1

// ---------------- common helpers ----------------
__device__ __forceinline__ void cp16(uint32_t dst_smem, const void* src) {
    asm volatile("cp.async.cg.shared.global [%0], [%1], 16;" :: "r"(dst_smem), "l"(src));
}
// cp.async with L2 cache-policy (evict_first for streaming bonds)
__device__ __forceinline__ void cp16_pol(uint32_t dst_smem, const void* src, uint64_t pol) {
    asm volatile("cp.async.cg.shared.global.L2::cache_hint [%0], [%1], 16, %2;"
                 :: "r"(dst_smem), "l"(src), "l"(pol));
}
__device__ __forceinline__ void cp_commit() { asm volatile("cp.async.commit_group;"); }
__device__ __forceinline__ void cp_wait0()  { asm volatile("cp.async.wait_group 0;"); }

__device__ __forceinline__ uint64_t policy_evict_first() {
    uint64_t p;
    asm volatile("createpolicy.fractional.L2::evict_first.b64 %0, 1.0;" : "=l"(p));
    return p;
}
__device__ __forceinline__ uint64_t policy_evict_last() {
    uint64_t p;
    asm volatile("createpolicy.fractional.L2::evict_last.b64 %0, 1.0;" : "=l"(p));
    return p;
}

// U read with evict_last (keep U resident in L2)
__device__ __forceinline__ float2 ldg_el(const float* p, uint64_t pol) {
    float2 v;
    asm volatile("ld.global.nc.L2::cache_hint.v2.f32 {%0,%1}, [%2], %3;"
                 : "=f"(v.x), "=f"(v.y) : "l"(p), "l"(pol));
    return v;
}
// U write with evict_last
__device__ __forceinline__ void stg_el(float* p, float x, float y, uint64_t pol) {
    asm volatile("st.global.L2::cache_hint.v2.f32 [%0], {%1,%2}, %3;"
                 :: "l"(p), "f"(x), "f"(y), "l"(pol) : "memory");
}

__device__ __forceinline__ void mma_tf32(float* c, const uint32_t* a, const uint32_t* b) {
    asm volatile(
        "mma.sync.aligned.m16n8k8.row.col.f32.tf32.tf32.f32 "
        "{%0,%1,%2,%3}, {%4,%5,%6,%7}, {%8,%9}, {%0,%1,%2,%3};"
        : "+f"(c[0]), "+f"(c[1]), "+f"(c[2]), "+f"(c[3])
        : "r"(a[0]), "r"(a[1]), "r"(a[2]), "r"(a[3]), "r"(b[0]), "r"(b[1]));
}

__device__ __forceinline__ void red_add_v2(float* p, float a, float b) {
    asm volatile("red.global.add.v2.f32 [%0], {%1, %2};" :: "l"(p), "f"(a), "f"(b) : "memory");
}

// ---------------- sort kernels ----------------
__global__ void hist_kernel(const int* __restrict__ idx1) {
    int e = blockIdx.x * blockDim.x + threadIdx.x;
    if (e < N_EDGES) atomicAdd(&g_count[idx1[e]], 1);
}

// per-block scan: g_count[i] -> local exclusive prefix; g_bsum[b] = block total
__global__ void scan_a_kernel() {
    __shared__ int s[256];
    int t = threadIdx.x, b = blockIdx.x;
    int i = b * 256 + t;
    int c = g_count[i];
    s[t] = c; __syncthreads();
#pragma unroll
    for (int d = 1; d < 256; d <<= 1) {
        int v = (t >= d) ? s[t - d] : 0; __syncthreads();
        s[t] += v; __syncthreads();
    }
    g_count[i] = s[t] - c;
    if (t == 255) g_bsum[b] = s[255];
}

// single-block exclusive scan of 196 block sums
__global__ void scan_b_kernel() {
    __shared__ int s[256];
    int t = threadIdx.x;
    int c = (t < 196) ? g_bsum[t] : 0;
    s[t] = c; __syncthreads();
#pragma unroll
    for (int d = 1; d < 256; d <<= 1) {
        int v = (t >= d) ? s[t - d] : 0; __syncthreads();
        s[t] += v; __syncthreads();
    }
    g_bsum[t] = s[t] - c;
}

// perm scatter: pos = blockoff + localexcl + in-bucket cursor
__global__ void perm_kernel(const int* __restrict__ idx1) {
    int e = blockIdx.x * blockDim.x + threadIdx.x;
    if (e < N_EDGES) {
        int n = idx1[e];
        int local = atomicAdd(&g_count[n], 1);
        g_perm[local + g_bsum[n >> 8]] = e;
    }
}

// ---------------- U precompute (fused: zero g_count + residual copy + GEMM) ----------------
// tile M=128, N=128 (grid.y=4 covers 512), K=128 in 4 stages of 32, double-buffered
#define UG_ASTR 36
#define UG_BSTR 136
#define UG_A0   0
#define UG_A1   4608
#define UG_B0   9216
#define UG_B1   13568
#define UG_SMEMF 17920

__global__ void __launch_bounds__(256) u_gemm_kernel(
    const float* __restrict__ sites,
    const float* __restrict__ W_sig, const float* __restrict__ b_sig,
    const float* __restrict__ W_soft, const float* __restrict__ b_soft,
    float* __restrict__ out)
{
    extern __shared__ float smf[];
    uint32_t sbase = (uint32_t)__cvta_generic_to_shared(smf);

    const int tid = threadIdx.x, wid = tid >> 5, lane = tid & 31;
    const int g = lane >> 2, cc = lane & 3;
    const int wm = wid >> 1, wn = wid & 1;        // 4x2 warp grid, warp tile 32x64
    const int bm = blockIdx.x, by = blockIdx.y;
    const int row0 = bm * 128;
    const uint64_t pol_last = policy_evict_last();

    // ---- fused housekeeping: zero g_count, residual copy out = sites ----
    {
        int gid = (by * gridDim.x + bm) * 256 + tid;
        int nthr = gridDim.x * gridDim.y * 256;
        if (gid < NB50) g_count[gid] = 0;
        const float4* s4 = (const float4*)sites;
        float4* o4 = (float4*)out;
        for (int i = gid; i < (N_NODES * 128) / 4; i += nthr) o4[i] = s4[i];
    }

    auto load_stage = [&](int s) {
        uint32_t abuf = sbase + (uint32_t)(((s & 1) ? UG_A1 : UG_A0) * 4);
        uint32_t bbuf = sbase + (uint32_t)(((s & 1) ? UG_B1 : UG_B0) * 4);
#pragma unroll
        for (int j = 0; j < 4; j++) {           // A: 128 rows x 32 fl = 1024 chunks
            int q = tid + j * 256;
            int r = q >> 3, cx = q & 7;
            int grow = row0 + r; if (grow >= N_NODES) grow = N_NODES - 1;
            cp16(abuf + (uint32_t)((r * UG_ASTR + cx * 4) * 4),
                 sites + (size_t)grow * 128 + s * 32 + cx * 4);
        }
#pragma unroll
        for (int j = 0; j < 4; j++) {           // B: 32 k x 128 phys cols = 1024 chunks
            int q = tid + j * 256;
            int k = q >> 5, cq = q & 31;
            int P0 = by * 128 + cq * 4;
            int slot = P0 >> 8, p = P0 & 255;
            int h = (p >> 2) & 1, qd = p >> 3;
            const float* W = h ? W_soft : W_sig;
            cp16(bbuf + (uint32_t)((k * UG_BSTR + cq * 4) * 4),
                 W + (size_t)(slot * 128 + s * 32 + k) * 128 + qd * 4);
        }
    };

    load_stage(0); cp_commit();
    load_stage(1); cp_commit();

    float acc[2][8][4];
#pragma unroll
    for (int mt = 0; mt < 2; mt++)
#pragma unroll
        for (int nt = 0; nt < 8; nt++)
#pragma unroll
            for (int u = 0; u < 4; u++) acc[mt][nt][u] = 0.0f;

    for (int s = 0; s < 4; ++s) {
        if (s < 3) { asm volatile("cp.async.wait_group 1;"); } else cp_wait0();
        __syncthreads();
        const float* As = smf + ((s & 1) ? UG_A1 : UG_A0);
        const float* Bs = smf + ((s & 1) ? UG_B1 : UG_B0);
#pragma unroll
        for (int k8 = 0; k8 < 4; k8++) {
            const int k0 = k8 * 8;
            uint32_t a[2][4];
#pragma unroll
            for (int mt = 0; mt < 2; mt++) {
                const uint32_t* ap = (const uint32_t*)(As + (32 * wm + 16 * mt + g) * UG_ASTR + k0 + cc);
                a[mt][0] = ap[0]; a[mt][1] = ap[8 * UG_ASTR];
                a[mt][2] = ap[4]; a[mt][3] = ap[8 * UG_ASTR + 4];
            }
            uint32_t b[8][2];
#pragma unroll
            for (int nt = 0; nt < 8; nt++) {
                const uint32_t* bp = (const uint32_t*)(Bs + (k0 + cc) * UG_BSTR + 64 * wn + 8 * nt + g);
                b[nt][0] = bp[0]; b[nt][1] = bp[4 * UG_BSTR];
            }
#pragma unroll
            for (int mt = 0; mt < 2; mt++)
#pragma unroll
                for (int nt = 0; nt < 8; nt++)
                    mma_tf32(acc[mt][nt], a[mt], b[nt]);
        }
        __syncthreads();
        if (s + 2 < 4) { load_stage(s + 2); cp_commit(); }
    }

    // epilogue: write U (+bias on slot1), evict_last so U is planted in L2
#pragma unroll
    for (int mt = 0; mt < 2; mt++) {
        int r_lo = 32 * wm + 16 * mt + g;
        int grow_lo = row0 + r_lo, grow_hi = grow_lo + 8;
#pragma unroll
        for (int nt = 0; nt < 8; nt++) {
            int col = 64 * wn + 8 * nt + 2 * cc;
            int P = by * 128 + col;
            float bb0 = 0.0f, bb1 = 0.0f;
            if (by < 2) {                        // slot1: fold bias
                int p = P & 255;
                int h = (p >> 2) & 1;
                int l = ((p >> 3) << 2) | (p & 3);
                const float* bv = h ? b_soft : b_sig;
                bb0 = bv[l]; bb1 = bv[l + 1];
            }
            if (grow_lo < N_NODES)
                stg_el(g_U + (size_t)grow_lo * 512 + P,
                       acc[mt][nt][0] + bb0, acc[mt][nt][1] + bb1, pol_last);
            if (grow_hi < N_NODES)
                stg_el(g_U + (size_t)grow_hi * 512 + P,
                       acc[mt][nt][2] + bb0, acc[mt][nt][3] + bb1, pol_last);
        }
    }
}

// ---------------- edge kernel (sorted): bonds[perm] @ Wb + gather(U) + gate + scatter ----------------
#define EG_ASTR  68
#define EG_BSTR  264
#define EG_OFF_B    0            // 64 x 264 = 16896 fl (loaded once)
#define EG_OFF_A0   16896        // 64 x 68 = 4352 fl per buffer
#define EG_OFF_IDX  25600        // 2 buffers x 192 ints: [perm 64 | i1 64 | i2 64]
#define EG_SMEMF    25984
#define EG_SMEMB    (EG_SMEMF * 4)   // 103936

__global__ void __launch_bounds__(256, 2) edge_gate_kernel(
    const float* __restrict__ bonds,
    const float* __restrict__ W_sig, const float* __restrict__ W_soft,
    const int* __restrict__ idx1, const int* __restrict__ idx2,
    float* __restrict__ out)
{
    extern __shared__ float smf[];
    uint32_t sbase = (uint32_t)__cvta_generic_to_shared(smf);

    const int tid = threadIdx.x, wid = tid >> 5, lane = tid & 31;
    const int g = lane >> 2, cc = lane & 3;
    const int wm = wid >> 2, wn = wid & 3;       // 2x4 warp grid, warp tile 32x64
    const uint64_t pol_first = policy_evict_first();
    const uint64_t pol_last  = policy_evict_last();

    // load B (Wb rows 256:320, phys-interleaved cols) once: 64 k x 256 phys = 4096 chunks
#pragma unroll
    for (int j = 0; j < 16; j++) {
        int q = tid + j * 256;
        int k = q >> 6, cq = q & 63;
        int h = cq & 1, qd = cq >> 1;
        const float* W = h ? W_soft : W_sig;
        cp16(sbase + (uint32_t)((k * EG_BSTR + cq * 4) * 4),
             W + (size_t)(256 + k) * 128 + qd * 4);
    }

    int* islot = (int*)(smf + EG_OFF_IDX);   // [buf*192 + {perm:0, i1:64, i2:128}]

    auto load_A_cp = [&](int buf) {          // gather bond rows via smem perm of this buffer
        const int* sp = islot + buf * 192;
        uint32_t abuf = sbase + (uint32_t)((EG_OFF_A0 + buf * 4352) * 4);
#pragma unroll
        for (int j = 0; j < 4; j++) {        // 64 rows x 64 fl = 1024 chunks
            int q = tid + j * 256;
            int r = q >> 4, cx = q & 15;
            cp16_pol(abuf + (uint32_t)((r * EG_ASTR + cx * 4) * 4),
                     bonds + (size_t)sp[r] * 64 + cx * 4, pol_first);
        }
    };

    // ---- prologue ----
    int tile = blockIdx.x;
    if (tid < 64) {
        int p = g_perm[tile * TILE_E + tid];
        islot[tid] = p; islot[64 + tid] = idx1[p]; islot[128 + tid] = idx2[p];
    }
    __syncthreads();
    load_A_cp(0); cp_commit();               // group 0: B + A(tile0)

    int p_r = 0, a_r = 0, b_r = 0;
    {
        int nx = tile + GRID_EDGE;
        if (tid < 64 && nx < NTILES) {
            p_r = g_perm[nx * TILE_E + tid]; a_r = idx1[p_r]; b_r = idx2[p_r];
        }
    }

    int it = 0;
    while (true) {
        int buf = it & 1;
        int next = tile + GRID_EDGE;
        bool have_next = (next < NTILES);

        cp_wait0(); __syncthreads();         // A(tile) ready; prior epilogue done

        if (have_next && tid < 64) {
            int* d = islot + (buf ^ 1) * 192;
            d[tid] = p_r; d[64 + tid] = a_r; d[128 + tid] = b_r;
        }
        __syncthreads();                     // perm(next) visible
        if (have_next) { load_A_cp(buf ^ 1); cp_commit(); }

        int nn = next + GRID_EDGE;
        if (have_next && tid < 64 && nn < NTILES) {   // hidden under GEMM
            p_r = g_perm[nn * TILE_E + tid]; a_r = idx1[p_r]; b_r = idx2[p_r];
        }

        const float* As = smf + EG_OFF_A0 + buf * 4352;
        const float* Bs = smf + EG_OFF_B;

        float acc[2][8][4];
#pragma unroll
        for (int mt = 0; mt < 2; mt++)
#pragma unroll
            for (int nt = 0; nt < 8; nt++)
#pragma unroll
                for (int u = 0; u < 4; u++) acc[mt][nt][u] = 0.0f;

#pragma unroll
        for (int k8 = 0; k8 < 8; k8++) {
            const int k0 = k8 * 8;
            uint32_t a[2][4];
#pragma unroll
            for (int mt = 0; mt < 2; mt++) {
                const uint32_t* ap = (const uint32_t*)(As + (32 * wm + 16 * mt + g) * EG_ASTR + k0 + cc);
                a[mt][0] = ap[0]; a[mt][1] = ap[8 * EG_ASTR];
                a[mt][2] = ap[4]; a[mt][3] = ap[8 * EG_ASTR + 4];
            }
            uint32_t b[8][2];
#pragma unroll
            for (int nt = 0; nt < 8; nt++) {
                const uint32_t* bp = (const uint32_t*)(Bs + (k0 + cc) * EG_BSTR + 64 * wn + 8 * nt + g);
                b[nt][0] = bp[0]; b[nt][1] = bp[4 * EG_BSTR];
            }
#pragma unroll
            for (int mt = 0; mt < 2; mt++)
#pragma unroll
                for (int nt = 0; nt < 8; nt++)
                    mma_tf32(acc[mt][nt], a[mt], b[nt]);
        }

        // ---- epilogue: + U1[i1] + U2[i2] (evict_last), in-register gate via shfl, v2 scatter ----
        const int* sidx = islot + buf * 192;
        const int cb = 64 * wn + 2 * cc;
#pragma unroll
        for (int mt = 0; mt < 2; mt++) {
            int r_lo = 32 * wm + 16 * mt + g;
            int r_hi = r_lo + 8;
            int i1lo = sidx[64 + r_lo], i2lo = sidx[128 + r_lo];
            int i1hi = sidx[64 + r_hi], i2hi = sidx[128 + r_hi];
            const float* U1lo = g_U + (size_t)i1lo * 512;
            const float* U2lo = g_U + (size_t)i2lo * 512 + 256;
            const float* U1hi = g_U + (size_t)i1hi * 512;
            const float* U2hi = g_U + (size_t)i2hi * 512 + 256;
            float* outlo = out + (size_t)i1lo * 128;
            float* outhi = out + (size_t)i1hi * 128;
#pragma unroll
            for (int nt = 0; nt < 8; nt++) {
                int c = cb + 8 * nt;
                float2 ua = ldg_el(U1lo + c, pol_last);
                float2 ub = ldg_el(U2lo + c, pol_last);
                float2 va = ldg_el(U1hi + c, pol_last);
                float2 vb = ldg_el(U2hi + c, pol_last);
                float x0 = acc[mt][nt][0] + ua.x + ub.x;
                float x1 = acc[mt][nt][1] + ua.y + ub.y;
                float y0 = acc[mt][nt][2] + va.x + vb.x;
                float y1 = acc[mt][nt][3] + va.y + vb.y;
                // exchange sig<->soft halves (cc^2 partner)
                float rx0 = __shfl_xor_sync(0xFFFFFFFFu, x0, 2);
                float rx1 = __shfl_xor_sync(0xFFFFFFFFu, x1, 2);
                float ry0 = __shfl_xor_sync(0xFFFFFFFFu, y0, 2);
                float ry1 = __shfl_xor_sync(0xFFFFFFFFu, y1, 2);
                float sg0, sg1, sf0, sf1;
                float* dst;
                if ((cc & 2) == 0) {   // compute row_lo: own = sig, recv = soft
                    sg0 = x0; sg1 = x1; sf0 = rx0; sf1 = rx1; dst = outlo;
                } else {               // compute row_hi: recv = sig, own = soft
                    sg0 = ry0; sg1 = ry1; sf0 = y0; sf1 = y1; dst = outhi;
                }
                float v0 = (1.0f / (1.0f + __expf(-sg0))) * fmaxf(sf0, 0.0f);
                float v1 = (1.0f / (1.0f + __expf(-sg1))) * fmaxf(sf1, 0.0f);
                int gcol = 32 * wn + 4 * nt + 2 * (cc & 1);
                red_add_v2(dst + gcol, v0, v1);
            }
        }

        if (!have_next) break;
        tile = next; ++it;
    }
}

// ---------------- launch ----------------
extern "C" void kernel_launch(void* const* d_in, const int* in_sizes, int n_in,
                              void* d_out, int out_size) {
    const float* sites  = (const float*)d_in[0];
    const float* bonds  = (const float*)d_in[1];
    const float* W_sig  = (const float*)d_in[2];
    const float* b_sig  = (const float*)d_in[3];
    const float* W_soft = (const float*)d_in[4];
    const float* b_soft = (const float*)d_in[5];
    const int*   idx1   = (const int*)d_in[6];
    const int*   idx2   = (const int*)d_in[7];
    float* out = (float*)d_out;

    cudaFuncSetAttribute(u_gemm_kernel, cudaFuncAttributeMaxDynamicSharedMemorySize, UG_SMEMF * 4);
    cudaFuncSetAttribute(edge_gate_kernel, cudaFuncAttributeMaxDynamicSharedMemorySize, EG_SMEMB);

    // 1) U = sites @ Wcat (fused: zero g_count + out=sites residual copy)
    u_gemm_kernel<<<dim3((N_NODES + 127) / 128, 4), 256, UG_SMEMF * 4>>>(
        sites, W_sig, b_sig, W_soft, b_soft, out);

    // 2-5) counting sort of edges by idx1
    hist_kernel<<<N_EDGES / 256, 256>>>(idx1);
    scan_a_kernel<<<NB50 / 256, 256>>>();
    scan_b_kernel<<<1, 256>>>();
    perm_kernel<<<N_EDGES / 256, 256>>>(idx1);

    // 6) edges (sorted): bonds[perm] @ Wb + U gather + gate + scatter
    edge_gate_kernel<<<GRID_EDGE, 256, EG_SMEMB>>>(
        bonds, W_sig, W_soft, idx1, idx2, out);
}

// round 11
// speedup vs baseline: 2.4127x; 1.0393x over previous
#include <cuda_runtime.h>
#include <cstdint>

// Problem constants
#define N_NODES   50000
#define N_EDGES   800000
#define TILE_E    64
#define NTILES    12500       // 800000 / 64
#define GRID_EDGE 296         // 2 CTAs x 148 SMs
#define NB50      50176       // 196 * 256 (padded node count for scan)

// ---- U table: [node][512] phys-interleaved; slot1(0:256)=U1(+bias), slot2(256:512)=U2
// phys col p in a 256 block: quad q=p>>3, half h=(p>>2)&1 (0=sig,1=soft), logical l=4q+(p&3)
static __device__ float g_U[(size_t)N_NODES * 512];
static __device__ int   g_count[NB50];     // hist -> local-exclusive scan -> perm cursors
static __device__ int   g_bsum[256];       // block sums -> exclusive block offsets
static __device__ int   g_perm[N_EDGES];   // edge ids sorted by idx1

// ---------------- common helpers ----------------
__device__ __forceinline__ void cp16(uint32_t dst_smem, const void* src) {
    asm volatile("cp.async.cg.shared.global [%0], [%1], 16;" :: "r"(dst_smem), "l"(src));
}
// cp.async with L2 cache-policy (evict_first for streaming bonds)
__device__ __forceinline__ void cp16_pol(uint32_t dst_smem, const void* src, uint64_t pol) {
    asm volatile("cp.async.cg.shared.global.L2::cache_hint [%0], [%1], 16, %2;"
                 :: "r"(dst_smem), "l"(src), "l"(pol));
}
__device__ __forceinline__ void cp_commit() { asm volatile("cp.async.commit_group;"); }
__device__ __forceinline__ void cp_wait0()  { asm volatile("cp.async.wait_group 0;"); }

__device__ __forceinline__ uint64_t policy_evict_first() {
    uint64_t p;
    asm volatile("createpolicy.fractional.L2::evict_first.b64 %0, 1.0;" : "=l"(p));
    return p;
}
__device__ __forceinline__ uint64_t policy_evict_last() {
    uint64_t p;
    asm volatile("createpolicy.fractional.L2::evict_last.b64 %0, 1.0;" : "=l"(p));
    return p;
}

// U read with evict_last (keep U resident in L2)
__device__ __forceinline__ float2 ldg_el(const float* p, uint64_t pol) {
    float2 v;
    asm volatile("ld.global.nc.L2::cache_hint.v2.f32 {%0,%1}, [%2], %3;"
                 : "=f"(v.x), "=f"(v.y) : "l"(p), "l"(pol));
    return v;
}
// U write with evict_last
__device__ __forceinline__ void stg_el(float* p, float x, float y, uint64_t pol) {
    asm volatile("st.global.L2::cache_hint.v2.f32 [%0], {%1,%2}, %3;"
                 :: "l"(p), "f"(x), "f"(y), "l"(pol) : "memory");
}

__device__ __forceinline__ void mma_tf32(float* c, const uint32_t* a, const uint32_t* b) {
    asm volatile(
        "mma.sync.aligned.m16n8k8.row.col.f32.tf32.tf32.f32 "
        "{%0,%1,%2,%3}, {%4,%5,%6,%7}, {%8,%9}, {%0,%1,%2,%3};"
        : "+f"(c[0]), "+f"(c[1]), "+f"(c[2]), "+f"(c[3])
        : "r"(a[0]), "r"(a[1]), "r"(a[2]), "r"(a[3]), "r"(b[0]), "r"(b[1]));
}

__device__ __forceinline__ void red_add_v2(float* p, float a, float b) {
    asm volatile("red.global.add.v2.f32 [%0], {%1, %2};" :: "l"(p), "f"(a), "f"(b) : "memory");
}

// ---------------- sort kernels ----------------
__global__ void hist_kernel(const int* __restrict__ idx1) {
    int e = blockIdx.x * blockDim.x + threadIdx.x;
    if (e < N_EDGES) atomicAdd(&g_count[idx1[e]], 1);
}

// per-block scan: g_count[i] -> local exclusive prefix; g_bsum[b] = block total
__global__ void scan_a_kernel() {
    __shared__ int s[256];
    int t = threadIdx.x, b = blockIdx.x;
    int i = b * 256 + t;
    int c = g_count[i];
    s[t] = c; __syncthreads();
#pragma unroll
    for (int d = 1; d < 256; d <<= 1) {
        int v = (t >= d) ? s[t - d] : 0; __syncthreads();
        s[t] += v; __syncthreads();
    }
    g_count[i] = s[t] - c;
    if (t == 255) g_bsum[b] = s[255];
}

// single-block exclusive scan of 196 block sums
__global__ void scan_b_kernel() {
    __shared__ int s[256];
    int t = threadIdx.x;
    int c = (t < 196) ? g_bsum[t] : 0;
    s[t] = c; __syncthreads();
#pragma unroll
    for (int d = 1; d < 256; d <<= 1) {
        int v = (t >= d) ? s[t - d] : 0; __syncthreads();
        s[t] += v; __syncthreads();
    }
    g_bsum[t] = s[t] - c;
}

// perm scatter: pos = blockoff + localexcl + in-bucket cursor
__global__ void perm_kernel(const int* __restrict__ idx1) {
    int e = blockIdx.x * blockDim.x + threadIdx.x;
    if (e < N_EDGES) {
        int n = idx1[e];
        int local = atomicAdd(&g_count[n], 1);
        g_perm[local + g_bsum[n >> 8]] = e;
    }
}

// ---------------- U precompute (fused: zero g_count + residual copy + GEMM) ----------------
// tile M=128, N=128 (grid.y=4 covers 512), K=128 in 4 stages of 32, double-buffered
#define UG_ASTR 36
#define UG_BSTR 136
#define UG_A0   0
#define UG_A1   4608
#define UG_B0   9216
#define UG_B1   13568
#define UG_SMEMF 17920

__global__ void __launch_bounds__(256) u_gemm_kernel(
    const float* __restrict__ sites,
    const float* __restrict__ W_sig, const float* __restrict__ b_sig,
    const float* __restrict__ W_soft, const float* __restrict__ b_soft,
    float* __restrict__ out)
{
    extern __shared__ float smf[];
    uint32_t sbase = (uint32_t)__cvta_generic_to_shared(smf);

    const int tid = threadIdx.x, wid = tid >> 5, lane = tid & 31;
    const int g = lane >> 2, cc = lane & 3;
    const int wm = wid >> 1, wn = wid & 1;        // 4x2 warp grid, warp tile 32x64
    const int bm = blockIdx.x, by = blockIdx.y;
    const int row0 = bm * 128;
    const uint64_t pol_last = policy_evict_last();

    // ---- fused housekeeping: zero g_count, residual copy out = sites ----
    {
        int gid = (by * gridDim.x + bm) * 256 + tid;
        int nthr = gridDim.x * gridDim.y * 256;
        if (gid < NB50) g_count[gid] = 0;
        const float4* s4 = (const float4*)sites;
        float4* o4 = (float4*)out;
        for (int i = gid; i < (N_NODES * 128) / 4; i += nthr) o4[i] = s4[i];
    }

    auto load_stage = [&](int s) {
        uint32_t abuf = sbase + (uint32_t)(((s & 1) ? UG_A1 : UG_A0) * 4);
        uint32_t bbuf = sbase + (uint32_t)(((s & 1) ? UG_B1 : UG_B0) * 4);
#pragma unroll
        for (int j = 0; j < 4; j++) {           // A: 128 rows x 32 fl = 1024 chunks
            int q = tid + j * 256;
            int r = q >> 3, cx = q & 7;
            int grow = row0 + r; if (grow >= N_NODES) grow = N_NODES - 1;
            cp16(abuf + (uint32_t)((r * UG_ASTR + cx * 4) * 4),
                 sites + (size_t)grow * 128 + s * 32 + cx * 4);
        }
#pragma unroll
        for (int j = 0; j < 4; j++) {           // B: 32 k x 128 phys cols = 1024 chunks
            int q = tid + j * 256;
            int k = q >> 5, cq = q & 31;
            int P0 = by * 128 + cq * 4;
            int slot = P0 >> 8, p = P0 & 255;
            int h = (p >> 2) & 1, qd = p >> 3;
            const float* W = h ? W_soft : W_sig;
            cp16(bbuf + (uint32_t)((k * UG_BSTR + cq * 4) * 4),
                 W + (size_t)(slot * 128 + s * 32 + k) * 128 + qd * 4);
        }
    };

    load_stage(0); cp_commit();
    load_stage(1); cp_commit();

    float acc[2][8][4];
#pragma unroll
    for (int mt = 0; mt < 2; mt++)
#pragma unroll
        for (int nt = 0; nt < 8; nt++)
#pragma unroll
            for (int u = 0; u < 4; u++) acc[mt][nt][u] = 0.0f;

    for (int s = 0; s < 4; ++s) {
        if (s < 3) { asm volatile("cp.async.wait_group 1;"); } else cp_wait0();
        __syncthreads();
        const float* As = smf + ((s & 1) ? UG_A1 : UG_A0);
        const float* Bs = smf + ((s & 1) ? UG_B1 : UG_B0);
#pragma unroll
        for (int k8 = 0; k8 < 4; k8++) {
            const int k0 = k8 * 8;
            uint32_t a[2][4];
#pragma unroll
            for (int mt = 0; mt < 2; mt++) {
                const uint32_t* ap = (const uint32_t*)(As + (32 * wm + 16 * mt + g) * UG_ASTR + k0 + cc);
                a[mt][0] = ap[0]; a[mt][1] = ap[8 * UG_ASTR];
                a[mt][2] = ap[4]; a[mt][3] = ap[8 * UG_ASTR + 4];
            }
            uint32_t b[8][2];
#pragma unroll
            for (int nt = 0; nt < 8; nt++) {
                const uint32_t* bp = (const uint32_t*)(Bs + (k0 + cc) * UG_BSTR + 64 * wn + 8 * nt + g);
                b[nt][0] = bp[0]; b[nt][1] = bp[4 * UG_BSTR];
            }
#pragma unroll
            for (int mt = 0; mt < 2; mt++)
#pragma unroll
                for (int nt = 0; nt < 8; nt++)
                    mma_tf32(acc[mt][nt], a[mt], b[nt]);
        }
        __syncthreads();
        if (s + 2 < 4) { load_stage(s + 2); cp_commit(); }
    }

    // epilogue: write U (+bias on slot1), evict_last so U is planted in L2
#pragma unroll
    for (int mt = 0; mt < 2; mt++) {
        int r_lo = 32 * wm + 16 * mt + g;
        int grow_lo = row0 + r_lo, grow_hi = grow_lo + 8;
#pragma unroll
        for (int nt = 0; nt < 8; nt++) {
            int col = 64 * wn + 8 * nt + 2 * cc;
            int P = by * 128 + col;
            float bb0 = 0.0f, bb1 = 0.0f;
            if (by < 2) {                        // slot1: fold bias
                int p = P & 255;
                int h = (p >> 2) & 1;
                int l = ((p >> 3) << 2) | (p & 3);
                const float* bv = h ? b_soft : b_sig;
                bb0 = bv[l]; bb1 = bv[l + 1];
            }
            if (grow_lo < N_NODES)
                stg_el(g_U + (size_t)grow_lo * 512 + P,
                       acc[mt][nt][0] + bb0, acc[mt][nt][1] + bb1, pol_last);
            if (grow_hi < N_NODES)
                stg_el(g_U + (size_t)grow_hi * 512 + P,
                       acc[mt][nt][2] + bb0, acc[mt][nt][3] + bb1, pol_last);
        }
    }
}

// ---------------- edge kernel (sorted): bonds[perm] @ Wb + gather(U) + gate + seg-reduce + scatter ----------------
#define EG_ASTR  68
#define EG_BSTR  264
#define EG_OFF_B    0            // 64 x 264 = 16896 fl (loaded once)
#define EG_OFF_A0   16896        // 64 x 68 = 4352 fl per buffer
#define EG_OFF_IDX  25600        // 2 buffers x 192 ints: [perm 64 | i1 64 | i2 64]
#define EG_SMEMF    25984
#define EG_SMEMB    (EG_SMEMF * 4)   // 103936

__global__ void __launch_bounds__(256, 2) edge_gate_kernel(
    const float* __restrict__ bonds,
    const float* __restrict__ W_sig, const float* __restrict__ W_soft,
    const int* __restrict__ idx1, const int* __restrict__ idx2,
    float* __restrict__ out)
{
    extern __shared__ float smf[];
    uint32_t sbase = (uint32_t)__cvta_generic_to_shared(smf);

    const int tid = threadIdx.x, wid = tid >> 5, lane = tid & 31;
    const int g = lane >> 2, cc = lane & 3;
    const int wm = wid >> 2, wn = wid & 3;       // 2x4 warp grid, warp tile 32x64
    const uint64_t pol_first = policy_evict_first();
    const uint64_t pol_last  = policy_evict_last();

    // segmented-reduction lane map: after the sig/soft exchange, this thread's
    // gated row within its 16-row mt-group is rr; lane(r) holds row r at col parity c0.
    const int c0 = cc & 1;
    const int rr = g + ((cc >> 1) << 3);         // 0..15
    int srcl[4];
#pragma unroll
    for (int st = 0; st < 4; st++) {
        int rp = (rr + (1 << st)) & 15;          // wrap; validity handled by samep
        srcl[st] = ((rp & 7) << 2) | ((rp >> 3) << 1) | c0;
    }

    // load B (Wb rows 256:320, phys-interleaved cols) once: 64 k x 256 phys = 4096 chunks
#pragma unroll
    for (int j = 0; j < 16; j++) {
        int q = tid + j * 256;
        int k = q >> 6, cq = q & 63;
        int h = cq & 1, qd = cq >> 1;
        const float* W = h ? W_soft : W_sig;
        cp16(sbase + (uint32_t)((k * EG_BSTR + cq * 4) * 4),
             W + (size_t)(256 + k) * 128 + qd * 4);
    }

    int* islot = (int*)(smf + EG_OFF_IDX);   // [buf*192 + {perm:0, i1:64, i2:128}]

    auto load_A_cp = [&](int buf) {          // gather bond rows via smem perm of this buffer
        const int* sp = islot + buf * 192;
        uint32_t abuf = sbase + (uint32_t)((EG_OFF_A0 + buf * 4352) * 4);
#pragma unroll
        for (int j = 0; j < 4; j++) {        // 64 rows x 64 fl = 1024 chunks
            int q = tid + j * 256;
            int r = q >> 4, cx = q & 15;
            cp16_pol(abuf + (uint32_t)((r * EG_ASTR + cx * 4) * 4),
                     bonds + (size_t)sp[r] * 64 + cx * 4, pol_first);
        }
    };

    // ---- prologue ----
    int tile = blockIdx.x;
    if (tid < 64) {
        int p = g_perm[tile * TILE_E + tid];
        islot[tid] = p; islot[64 + tid] = idx1[p]; islot[128 + tid] = idx2[p];
    }
    __syncthreads();
    load_A_cp(0); cp_commit();               // group 0: B + A(tile0)

    int p_r = 0, a_r = 0, b_r = 0;
    {
        int nx = tile + GRID_EDGE;
        if (tid < 64 && nx < NTILES) {
            p_r = g_perm[nx * TILE_E + tid]; a_r = idx1[p_r]; b_r = idx2[p_r];
        }
    }

    int it = 0;
    while (true) {
        int buf = it & 1;
        int next = tile + GRID_EDGE;
        bool have_next = (next < NTILES);

        cp_wait0(); __syncthreads();         // A(tile) ready; prior epilogue done

        if (have_next && tid < 64) {
            int* d = islot + (buf ^ 1) * 192;
            d[tid] = p_r; d[64 + tid] = a_r; d[128 + tid] = b_r;
        }
        __syncthreads();                     // perm(next) visible
        if (have_next) { load_A_cp(buf ^ 1); cp_commit(); }

        int nn = next + GRID_EDGE;
        if (have_next && tid < 64 && nn < NTILES) {   // hidden under GEMM
            p_r = g_perm[nn * TILE_E + tid]; a_r = idx1[p_r]; b_r = idx2[p_r];
        }

        const float* As = smf + EG_OFF_A0 + buf * 4352;
        const float* Bs = smf + EG_OFF_B;

        float acc[2][8][4];
#pragma unroll
        for (int mt = 0; mt < 2; mt++)
#pragma unroll
            for (int nt = 0; nt < 8; nt++)
#pragma unroll
                for (int u = 0; u < 4; u++) acc[mt][nt][u] = 0.0f;

#pragma unroll
        for (int k8 = 0; k8 < 8; k8++) {
            const int k0 = k8 * 8;
            uint32_t a[2][4];
#pragma unroll
            for (int mt = 0; mt < 2; mt++) {
                const uint32_t* ap = (const uint32_t*)(As + (32 * wm + 16 * mt + g) * EG_ASTR + k0 + cc);
                a[mt][0] = ap[0]; a[mt][1] = ap[8 * EG_ASTR];
                a[mt][2] = ap[4]; a[mt][3] = ap[8 * EG_ASTR + 4];
            }
            uint32_t b[8][2];
#pragma unroll
            for (int nt = 0; nt < 8; nt++) {
                const uint32_t* bp = (const uint32_t*)(Bs + (k0 + cc) * EG_BSTR + 64 * wn + 8 * nt + g);
                b[nt][0] = bp[0]; b[nt][1] = bp[4 * EG_BSTR];
            }
#pragma unroll
            for (int mt = 0; mt < 2; mt++)
#pragma unroll
                for (int nt = 0; nt < 8; nt++)
                    mma_tf32(acc[mt][nt], a[mt], b[nt]);
        }

        // ---- epilogue: + U1[i1] + U2[i2], gate via shfl, SEGMENTED REDUCE, head-only scatter ----
        const int* sidx = islot + buf * 192;
        const int cb = 64 * wn + 2 * cc;
#pragma unroll
        for (int mt = 0; mt < 2; mt++) {
            int r_lo = 32 * wm + 16 * mt + g;
            int r_hi = r_lo + 8;
            int i1lo = sidx[64 + r_lo], i2lo = sidx[128 + r_lo];
            int i1hi = sidx[64 + r_hi], i2hi = sidx[128 + r_hi];
            const float* U1lo = g_U + (size_t)i1lo * 512;
            const float* U2lo = g_U + (size_t)i2lo * 512 + 256;
            const float* U1hi = g_U + (size_t)i1hi * 512;
            const float* U2hi = g_U + (size_t)i2hi * 512 + 256;
            float* outlo = out + (size_t)i1lo * 128;
            float* outhi = out + (size_t)i1hi * 128;

            // seg info for this mt-group (row rr within group, global tile row)
            int row_g = 32 * wm + 16 * mt + rr;
            int my_i1 = (cc & 2) ? i1hi : i1lo;
            bool head = (rr == 0) || (sidx[64 + row_g - 1] != my_i1);
            bool samep[4];
#pragma unroll
            for (int st = 0; st < 4; st++) {
                int i1p = __shfl_sync(0xFFFFFFFFu, my_i1, srcl[st]);
                samep[st] = ((rr + (1 << st)) < 16) && (i1p == my_i1);
            }
            float* dst = (cc & 2) ? outhi : outlo;

#pragma unroll
            for (int nt = 0; nt < 8; nt++) {
                int c = cb + 8 * nt;
                float2 ua = ldg_el(U1lo + c, pol_last);
                float2 ub = ldg_el(U2lo + c, pol_last);
                float2 va = ldg_el(U1hi + c, pol_last);
                float2 vb = ldg_el(U2hi + c, pol_last);
                float x0 = acc[mt][nt][0] + ua.x + ub.x;
                float x1 = acc[mt][nt][1] + ua.y + ub.y;
                float y0 = acc[mt][nt][2] + va.x + vb.x;
                float y1 = acc[mt][nt][3] + va.y + vb.y;
                // exchange sig<->soft halves (cc^2 partner)
                float rx0 = __shfl_xor_sync(0xFFFFFFFFu, x0, 2);
                float rx1 = __shfl_xor_sync(0xFFFFFFFFu, x1, 2);
                float ry0 = __shfl_xor_sync(0xFFFFFFFFu, y0, 2);
                float ry1 = __shfl_xor_sync(0xFFFFFFFFu, y1, 2);
                float sg0, sg1, sf0, sf1;
                if ((cc & 2) == 0) {   // compute row_lo: own = sig, recv = soft
                    sg0 = x0; sg1 = x1; sf0 = rx0; sf1 = rx1;
                } else {               // compute row_hi: recv = sig, own = soft
                    sg0 = ry0; sg1 = ry1; sf0 = y0; sf1 = y1;
                }
                float v0 = (1.0f / (1.0f + __expf(-sg0))) * fmaxf(sf0, 0.0f);
                float v1 = (1.0f / (1.0f + __expf(-sg1))) * fmaxf(sf1, 0.0f);

                // segmented suffix-sum over rows of equal i1 (sorted, contiguous)
#pragma unroll
                for (int st = 0; st < 4; st++) {
                    float t0 = __shfl_sync(0xFFFFFFFFu, v0, srcl[st]);
                    float t1 = __shfl_sync(0xFFFFFFFFu, v1, srcl[st]);
                    if (samep[st]) { v0 += t0; v1 += t1; }
                }
                if (head) {
                    int gcol = 32 * wn + 4 * nt + 2 * c0;
                    red_add_v2(dst + gcol, v0, v1);
                }
            }
        }

        if (!have_next) break;
        tile = next; ++it;
    }
}

// ---------------- launch ----------------
extern "C" void kernel_launch(void* const* d_in, const int* in_sizes, int n_in,
                              void* d_out, int out_size) {
    const float* sites  = (const float*)d_in[0];
    const float* bonds  = (const float*)d_in[1];
    const float* W_sig  = (const float*)d_in[2];
    const float* b_sig  = (const float*)d_in[3];
    const float* W_soft = (const float*)d_in[4];
    const float* b_soft = (const float*)d_in[5];
    const int*   idx1   = (const int*)d_in[6];
    const int*   idx2   = (const int*)d_in[7];
    float* out = (float*)d_out;

    cudaFuncSetAttribute(u_gemm_kernel, cudaFuncAttributeMaxDynamicSharedMemorySize, UG_SMEMF * 4);
    cudaFuncSetAttribute(edge_gate_kernel, cudaFuncAttributeMaxDynamicSharedMemorySize, EG_SMEMB);

    // 1) U = sites @ Wcat (fused: zero g_count + out=sites residual copy)
    u_gemm_kernel<<<dim3((N_NODES + 127) / 128, 4), 256, UG_SMEMF * 4>>>(
        sites, W_sig, b_sig, W_soft, b_soft, out);

    // 2-5) counting sort of edges by idx1
    hist_kernel<<<N_EDGES / 256, 256>>>(idx1);
    scan_a_kernel<<<NB50 / 256, 256>>>();
    scan_b_kernel<<<1, 256>>>();
    perm_kernel<<<N_EDGES / 256, 256>>>(idx1);

    // 6) edges (sorted): bonds[perm] @ Wb + U gather + gate + seg-reduce + scatter
    edge_gate_kernel<<<GRID_EDGE, 256, EG_SMEMB>>>(
        bonds, W_sig, W_soft, idx1, idx2, out);
}